// round 17
// baseline (speedup 1.0000x reference)
#include <cuda_runtime.h>
#include <cuda_bf16.h>
#include <cuda_fp16.h>
#include <math.h>
#include <stdint.h>

#define NB 8
#define HH 128
#define WW 128
#define NC 192
#define C3 576
#define HEADS 4
#define CH 48
#define HW 16384
#define BNT 32
#define KDIM 192

// ---------------- scratch ----------------
__device__ __half g_qkv_h[(size_t)NB * HW * C3];      // qkv intermediate, fp16
__device__ __nv_bfloat16 g_qh[(size_t)NB * HW * NC];
__device__ __nv_bfloat16 g_ql[(size_t)NB * HW * NC];
__device__ __nv_bfloat16 g_kh[(size_t)NB * HW * NC];
__device__ __nv_bfloat16 g_kl[(size_t)NB * HW * NC];
__device__ __half g_v_h[(size_t)NB * HW * NC];        // v, fp16
__device__ __half g_o_h[(size_t)NB * HW * NC];        // attn@V output, fp16
__device__ float g_attn[BNT * CH * CH];
__device__ float g_ssq_q[BNT * CH];
__device__ float g_ssq_k[BNT * CH];
// GEMM weights: fp16 (single plane), [N][K]
__device__ __half g_wqkv[C3 * KDIM];
__device__ __half g_wproj[NC * KDIM];

// ---------------- helpers ----------------
__device__ __forceinline__ uint32_t smem_u32(const void* p) {
    uint32_t a;
    asm("{ .reg .u64 t; cvta.to.shared.u64 t, %1; cvt.u32.u64 %0, t; }" : "=r"(a) : "l"(p));
    return a;
}
__device__ __forceinline__ uint32_t pk_hi(float a, float b) {   // bf16 pack (q/k path)
    __nv_bfloat16 ha = __float2bfloat16(a), hb = __float2bfloat16(b);
    uint16_t ra = *(uint16_t*)&ha, rb = *(uint16_t*)&hb;
    return (uint32_t)ra | ((uint32_t)rb << 16);
}
__device__ __forceinline__ uint32_t pk_lo(float a, float b) {
    __nv_bfloat16 ha = __float2bfloat16(a), hb = __float2bfloat16(b);
    float la = a - __bfloat162float(ha), lb = b - __bfloat162float(hb);
    __nv_bfloat16 xa = __float2bfloat16(la), xb = __float2bfloat16(lb);
    uint16_t ra = *(uint16_t*)&xa, rb = *(uint16_t*)&xb;
    return (uint32_t)ra | ((uint32_t)rb << 16);
}
__device__ __forceinline__ uint32_t pkh(float a, float b) {     // fp16x2 pack
    __half2 h = __floats2half2_rn(a, b);
    return *(uint32_t*)&h;
}
__device__ __forceinline__ float bf_lo(uint32_t v) { return __uint_as_float(v << 16); }
__device__ __forceinline__ float bf_hi(uint32_t v) { return __uint_as_float(v & 0xffff0000u); }

__device__ __forceinline__ void mma16816(float* c, const uint32_t* a, const uint32_t* b) {
    asm volatile(
        "mma.sync.aligned.m16n8k16.row.col.f32.bf16.bf16.f32 "
        "{%0,%1,%2,%3}, {%4,%5,%6,%7}, {%8,%9}, {%0,%1,%2,%3};\n"
        : "+f"(c[0]), "+f"(c[1]), "+f"(c[2]), "+f"(c[3])
        : "r"(a[0]), "r"(a[1]), "r"(a[2]), "r"(a[3]), "r"(b[0]), "r"(b[1]));
}
__device__ __forceinline__ void mma16816h(float* c, const uint32_t* a, const uint32_t* b) {
    asm volatile(
        "mma.sync.aligned.m16n8k16.row.col.f32.f16.f16.f32 "
        "{%0,%1,%2,%3}, {%4,%5,%6,%7}, {%8,%9}, {%0,%1,%2,%3};\n"
        : "+f"(c[0]), "+f"(c[1]), "+f"(c[2]), "+f"(c[3])
        : "r"(a[0]), "r"(a[1]), "r"(a[2]), "r"(a[3]), "r"(b[0]), "r"(b[1]));
}
__device__ __forceinline__ void ldmx4(uint32_t* r, uint32_t addr) {
    asm volatile("ldmatrix.sync.aligned.m8n8.x4.shared.b16 {%0,%1,%2,%3}, [%4];"
        : "=r"(r[0]), "=r"(r[1]), "=r"(r[2]), "=r"(r[3]) : "r"(addr));
}
#define CP_ASYNC16(dst, src) asm volatile("cp.async.ca.shared.global [%0], [%1], 16;" :: "r"(dst), "l"(src))
#define CP_COMMIT()          asm volatile("cp.async.commit_group;" ::: "memory")
#define CP_WAIT(n)           asm volatile("cp.async.wait_group %0;" :: "n"(n) : "memory")

// ---------------- weight prep ----------------
__global__ void wprep_qkvw_kernel(const float* __restrict__ qkvw)
{
    int i = blockIdx.x * 256 + threadIdx.x;
    if (i < C3 * KDIM) {
        int n = i / KDIM, k = i % KDIM;
        g_wqkv[i] = __float2half_rn(qkvw[(size_t)k * C3 + n]);
    }
}
__global__ void wprep_projw_kernel(const float* __restrict__ projw)
{
    int i = blockIdx.x * 256 + threadIdx.x;
    if (i < NC * KDIM) {
        int n = i / KDIM, k = i % KDIM;
        g_wproj[i] = __float2half_rn(projw[(size_t)k * NC + n]);
    }
}
__global__ void zero_kernel()
{
    int i = blockIdx.x * 256 + threadIdx.x;
    if (i < BNT * CH * CH) g_attn[i] = 0.f;
    if (i < BNT * CH) { g_ssq_q[i] = 0.f; g_ssq_k[i] = 0.f; }
}

// ---------------- fp16 single-pass GEMM, warp tile 64x32 ----------------
#define ASTRIDE 200
#define ROWB    (ASTRIDE * 2)          // 400 bytes per row
#define OFF_A   0                       // 128 * 400 = 51200
#define OFF_B   (128 * ROWB)            // 51200
#define GEMM_SMEM (128 * ROWB + 64 * ROWB)   // 76800

template<bool AHALF, bool OUTHALF>
__global__ __launch_bounds__(128, 2) void gemm_fp16_1p(
    const void* __restrict__ Aptr, const __half* __restrict__ W,
    void* __restrict__ Coutp, int Ntot)
{
    extern __shared__ char smem[];
    const uint32_t sbase = smem_u32(smem);
    const uint32_t sA = sbase + OFF_A;
    const uint32_t sB = sbase + OFF_B;

    const int t = threadIdx.x;
    const int warp = t >> 5, lane = t & 31;
    const int grp = lane >> 2, tig = lane & 3;
    const int warpM = warp & 1, warpN = warp >> 1;      // 2 x 2, warp tile 64x32
    const size_t m0 = (size_t)blockIdx.x * 128;
    const int nChunks = Ntot >> 6;

    const uint32_t aOff = (uint32_t)(warpM * 64 + (lane & 15)) * ROWB + ((lane >> 4) * 16);
    const uint32_t bOff = (uint32_t)(warpN * 32 + ((lane >> 4) * 8) + (lane & 7)) * ROWB
                          + (((lane >> 3) & 1) * 16);

    // ---- issue B chunk 0 load ----
    {
        const uint4* bw = (const uint4*)W;
#pragma unroll
        for (int i = t; i < 1536; i += 128) {
            int row = i / 24, cb = (i % 24) * 16;
            CP_ASYNC16(sB + (uint32_t)row * ROWB + cb, bw + i);
        }
        CP_COMMIT();
    }
    // ---- A tile ----
    if (AHALF) {
        const __half* Ah = (const __half*)Aptr;
#pragma unroll
        for (int i = t; i < 3072; i += 128) {
            int row = i / 24, seg = i % 24;
            const uint4* src = (const uint4*)(Ah + (m0 + row) * KDIM) + seg;
            CP_ASYNC16(sA + (uint32_t)row * ROWB + seg * 16, src);
        }
        CP_COMMIT();
    } else {
        const float* Af = (const float*)Aptr;
        int row = t;
        const float4* ar = (const float4*)(Af + (m0 + row) * KDIM);
        __half* ap = (__half*)(smem + OFF_A) + row * ASTRIDE;
#pragma unroll
        for (int j = 0; j < 48; j++) {
            float4 v = ar[j];
            *(uint32_t*)(ap + j * 4)     = pkh(v.x, v.y);
            *(uint32_t*)(ap + j * 4 + 2) = pkh(v.z, v.w);
        }
    }
    CP_WAIT(0);
    __syncthreads();

    float c[4][4][4];

    for (int nc = 0; nc < nChunks; nc++) {
#pragma unroll
        for (int mi = 0; mi < 4; mi++)
#pragma unroll
            for (int nj = 0; nj < 4; nj++)
#pragma unroll
                for (int j = 0; j < 4; j++) c[mi][nj][j] = 0.f;

#pragma unroll
        for (int ks = 0; ks < 12; ks++) {
            const uint32_t k32 = ks * 32;
            uint32_t a[4][4], b0[4], b1[4];
#pragma unroll
            for (int mi = 0; mi < 4; mi++)
                ldmx4(a[mi], sA + aOff + (uint32_t)(mi * 16) * ROWB + k32);
            ldmx4(b0, sB + bOff + k32);
            ldmx4(b1, sB + bOff + 16 * ROWB + k32);
#pragma unroll
            for (int mi = 0; mi < 4; mi++) {
                mma16816h(c[mi][0], a[mi], &b0[0]);
                mma16816h(c[mi][1], a[mi], &b0[2]);
                mma16816h(c[mi][2], a[mi], &b1[0]);
                mma16816h(c[mi][3], a[mi], &b1[2]);
            }
        }
        __syncthreads();

        if (nc + 1 < nChunks) {
            const uint4* bw = (const uint4*)(W + (size_t)(nc + 1) * 64 * KDIM);
#pragma unroll
            for (int i = t; i < 1536; i += 128) {
                int row = i / 24, cb = (i % 24) * 16;
                CP_ASYNC16(sB + (uint32_t)row * ROWB + cb, bw + i);
            }
            CP_COMMIT();
        }

        const int n0 = nc * 64;
#pragma unroll
        for (int mi = 0; mi < 4; mi++) {
            size_t row = m0 + warpM * 64 + mi * 16 + grp;
#pragma unroll
            for (int nj = 0; nj < 4; nj++) {
                int col = n0 + warpN * 32 + nj * 8 + tig * 2;
                if (OUTHALF) {
                    __half* co = (__half*)Coutp;
                    *(uint32_t*)(co + row * Ntot + col)       = pkh(c[mi][nj][0], c[mi][nj][1]);
                    *(uint32_t*)(co + (row + 8) * Ntot + col) = pkh(c[mi][nj][2], c[mi][nj][3]);
                } else {
                    float* co = (float*)Coutp;
                    *(float2*)(co + row * Ntot + col) = make_float2(c[mi][nj][0], c[mi][nj][1]);
                    *(float2*)(co + (row + 8) * Ntot + col) = make_float2(c[mi][nj][2], c[mi][nj][3]);
                }
            }
        }
        CP_WAIT(0);
        __syncthreads();
    }
}

// ---------------- tiled depthwise 3x3 v2: channel-major lanes, coalesced ----------------
// grid (18 cgroups, 64 tiles, NB); 256 threads. One 64B (32-half) channel slice per block,
// 16x16 output tile with 18x18 halo in smem. Lane map c4 = t&3 -> contiguous 64B runs.
__global__ __launch_bounds__(256) void dwconv_tiled2_kernel(const float* __restrict__ w)
{
    __shared__ uint4 sm[324 * 4];        // 18*18 pixels * 4 uint4 (32 halves) = 20736 B
    __shared__ float wsm[9 * 32];        // 1152 B

    const int cgB = blockIdx.x;          // 0..17
    const int tile = blockIdx.y;         // 0..63
    const int b = blockIdx.z;
    const int ty0 = (tile >> 3) * 16, tx0 = (tile & 7) * 16;
    const int t = threadIdx.x;
    const int ch0 = cgB * 32;

    // FIX (R16 bug): 288 weight entries > 256 threads -> grid-stride loop
    for (int i = t; i < 288; i += 256)
        wsm[i] = w[(i >> 5) * C3 + ch0 + (i & 31)];

    for (int i = t; i < 1296; i += 256) {      // 324 pixels * 4 uint4
        int c4 = i & 3, pix = i >> 2;
        int py = pix / 18, px = pix - py * 18;
        int gy = ty0 + py - 1, gx = tx0 + px - 1;
        uint4 v = make_uint4(0u, 0u, 0u, 0u);
        if ((unsigned)gy < 128u && (unsigned)gx < 128u)
            v = *(const uint4*)(g_qkv_h + ((size_t)((b * HH + gy) * WW + gx)) * C3 + ch0 + c4 * 8);
        sm[pix * 4 + c4] = v;
    }
    __syncthreads();

    const int plane = cgB / 6;               // 0=q, 1=k, 2=v
    const int cc0 = ch0 - plane * NC;

#pragma unroll
    for (int it = 0; it < 4; it++) {
        int po = it * 64 + (t >> 2);         // output pixel 0..255
        int c4 = t & 3;
        int oy = po >> 4, ox = po & 15;
        float acc[8];
#pragma unroll
        for (int j = 0; j < 8; j++) acc[j] = 0.f;
#pragma unroll
        for (int dy = 0; dy < 3; dy++)
#pragma unroll
            for (int dx = 0; dx < 3; dx++) {
                uint4 hv = sm[((oy + dy) * 18 + ox + dx) * 4 + c4];
                const float* wp = wsm + (dy * 3 + dx) * 32 + c4 * 8;
                float2 f0 = __half22float2(*(__half2*)&hv.x);
                float2 f1 = __half22float2(*(__half2*)&hv.y);
                float2 f2 = __half22float2(*(__half2*)&hv.z);
                float2 f3 = __half22float2(*(__half2*)&hv.w);
                acc[0] = fmaf(f0.x, wp[0], acc[0]);
                acc[1] = fmaf(f0.y, wp[1], acc[1]);
                acc[2] = fmaf(f1.x, wp[2], acc[2]);
                acc[3] = fmaf(f1.y, wp[3], acc[3]);
                acc[4] = fmaf(f2.x, wp[4], acc[4]);
                acc[5] = fmaf(f2.y, wp[5], acc[5]);
                acc[6] = fmaf(f3.x, wp[6], acc[6]);
                acc[7] = fmaf(f3.y, wp[7], acc[7]);
            }
        size_t p = (size_t)(b * HH + ty0 + oy) * WW + tx0 + ox;
        int cc = cc0 + c4 * 8;
        if (plane == 0) {
            *(uint4*)&g_qh[p * NC + cc] = make_uint4(
                pk_hi(acc[0], acc[1]), pk_hi(acc[2], acc[3]),
                pk_hi(acc[4], acc[5]), pk_hi(acc[6], acc[7]));
            *(uint4*)&g_ql[p * NC + cc] = make_uint4(
                pk_lo(acc[0], acc[1]), pk_lo(acc[2], acc[3]),
                pk_lo(acc[4], acc[5]), pk_lo(acc[6], acc[7]));
        } else if (plane == 1) {
            *(uint4*)&g_kh[p * NC + cc] = make_uint4(
                pk_hi(acc[0], acc[1]), pk_hi(acc[2], acc[3]),
                pk_hi(acc[4], acc[5]), pk_hi(acc[6], acc[7]));
            *(uint4*)&g_kl[p * NC + cc] = make_uint4(
                pk_lo(acc[0], acc[1]), pk_lo(acc[2], acc[3]),
                pk_lo(acc[4], acc[5]), pk_lo(acc[6], acc[7]));
        } else {
            *(uint4*)&g_v_h[p * NC + cc] = make_uint4(
                pkh(acc[0], acc[1]), pkh(acc[2], acc[3]),
                pkh(acc[4], acc[5]), pkh(acc[6], acc[7]));
        }
    }
}

// ---------------- QK^T via mma.sync bf16-split + fused ssq ----------------
#define QK_PLANE 25344                     // 48 rows * 528 bytes
#define QK_SMEM  (4 * QK_PLANE)            // 101376

__global__ __launch_bounds__(256) void qk_mma_kernel()
{
    extern __shared__ char qsm[];
    const uint32_t sb = smem_u32(qsm);
    const int t = threadIdx.x, lane = t & 31, warp = t >> 5;
    const int grp = lane >> 2, tig = lane & 3;
    const int bn = blockIdx.x;
    const int sbase0 = blockIdx.y * 2048;

    const uint32_t aAddr = sb + (uint32_t)(lane & 15) * 528 + warp * 64 + ((lane >> 4) * 16);
    const uint32_t bAddr = sb + (uint32_t)(((lane >> 4) * 8) + (lane & 7)) * 528 + warp * 64
                           + (((lane >> 3) & 1) * 16);

    float c[3][6][4];
#pragma unroll
    for (int mi = 0; mi < 3; mi++)
#pragma unroll
        for (int nj = 0; nj < 6; nj++)
#pragma unroll
            for (int j = 0; j < 4; j++) c[mi][nj][j] = 0.f;
    float sq[3][2] = {{0.f,0.f},{0.f,0.f},{0.f,0.f}};
    float sk[3][2] = {{0.f,0.f},{0.f,0.f},{0.f,0.f}};

    for (int stage = 0; stage < 8; stage++) {
        const int sbase = sbase0 + stage * 256;
        const __nv_bfloat16* gp0 = g_qh; const __nv_bfloat16* gp1 = g_ql;
        const __nv_bfloat16* gp2 = g_kh; const __nv_bfloat16* gp3 = g_kl;
#pragma unroll
        for (int pl = 0; pl < 4; pl++) {
            const __nv_bfloat16* gp = (pl == 0) ? gp0 : (pl == 1) ? gp1 : (pl == 2) ? gp2 : gp3;
            uint32_t sp = sb + pl * QK_PLANE;
            for (int i = t; i < 1536; i += 256) {
                int r = i >> 5, seg = i & 31;
                const void* src = gp + (((size_t)(bn * 48 + r)) << 14) + sbase + seg * 8;
                CP_ASYNC16(sp + (uint32_t)r * 528 + seg * 16, src);
            }
        }
        CP_COMMIT();
        CP_WAIT(0);
        __syncthreads();

#pragma unroll
        for (int ks = 0; ks < 2; ks++) {
            const uint32_t kb = ks * 32;
            uint32_t ah[3][4], al[3][4], bh[3][4], bl[3][4];
#pragma unroll
            for (int mi = 0; mi < 3; mi++) {
                ldmx4(ah[mi], aAddr + (uint32_t)(mi * 16) * 528 + kb);
                ldmx4(al[mi], aAddr + QK_PLANE + (uint32_t)(mi * 16) * 528 + kb);
            }
#pragma unroll
            for (int pj = 0; pj < 3; pj++) {
                ldmx4(bh[pj], bAddr + 2 * QK_PLANE + (uint32_t)(pj * 16) * 528 + kb);
                ldmx4(bl[pj], bAddr + 3 * QK_PLANE + (uint32_t)(pj * 16) * 528 + kb);
            }
#pragma unroll
            for (int mi = 0; mi < 3; mi++)
#pragma unroll
                for (int r = 0; r < 4; r++) {
                    float f0 = bf_lo(ah[mi][r]) + bf_lo(al[mi][r]);
                    float f1 = bf_hi(ah[mi][r]) + bf_hi(al[mi][r]);
                    sq[mi][r & 1] = fmaf(f0, f0, fmaf(f1, f1, sq[mi][r & 1]));
                }
#pragma unroll
            for (int pj = 0; pj < 3; pj++)
#pragma unroll
                for (int r = 0; r < 4; r++) {
                    float f0 = bf_lo(bh[pj][r]) + bf_lo(bl[pj][r]);
                    float f1 = bf_hi(bh[pj][r]) + bf_hi(bl[pj][r]);
                    sk[pj][r >> 1] = fmaf(f0, f0, fmaf(f1, f1, sk[pj][r >> 1]));
                }
#pragma unroll
            for (int mi = 0; mi < 3; mi++)
#pragma unroll
                for (int pj = 0; pj < 3; pj++) {
                    mma16816(c[mi][2 * pj],     ah[mi], &bh[pj][0]);
                    mma16816(c[mi][2 * pj + 1], ah[mi], &bh[pj][2]);
                }
#pragma unroll
            for (int mi = 0; mi < 3; mi++)
#pragma unroll
                for (int pj = 0; pj < 3; pj++) {
                    mma16816(c[mi][2 * pj],     ah[mi], &bl[pj][0]);
                    mma16816(c[mi][2 * pj + 1], ah[mi], &bl[pj][2]);
                }
#pragma unroll
            for (int mi = 0; mi < 3; mi++)
#pragma unroll
                for (int pj = 0; pj < 3; pj++) {
                    mma16816(c[mi][2 * pj],     al[mi], &bh[pj][0]);
                    mma16816(c[mi][2 * pj + 1], al[mi], &bh[pj][2]);
                }
        }
        __syncthreads();
    }

    float* attn_s = (float*)qsm;
    float* ssq_qs = attn_s + 2304;
    float* ssq_ks = ssq_qs + 48;
    for (int i = t; i < 2400; i += 256) attn_s[i] = 0.f;
    __syncthreads();

#pragma unroll
    for (int mi = 0; mi < 3; mi++)
#pragma unroll
        for (int nj = 0; nj < 6; nj++) {
            int row = mi * 16 + grp, col = nj * 8 + tig * 2;
            atomicAdd(&attn_s[row * 48 + col],           c[mi][nj][0]);
            atomicAdd(&attn_s[row * 48 + col + 1],       c[mi][nj][1]);
            atomicAdd(&attn_s[(row + 8) * 48 + col],     c[mi][nj][2]);
            atomicAdd(&attn_s[(row + 8) * 48 + col + 1], c[mi][nj][3]);
        }
#pragma unroll
    for (int mi = 0; mi < 3; mi++)
#pragma unroll
        for (int h = 0; h < 2; h++) {
            float v = sq[mi][h];
            v += __shfl_xor_sync(~0u, v, 1);
            v += __shfl_xor_sync(~0u, v, 2);
            if (tig == 0) atomicAdd(&ssq_qs[mi * 16 + h * 8 + grp], v);
            float u = sk[mi][h];
            u += __shfl_xor_sync(~0u, u, 1);
            u += __shfl_xor_sync(~0u, u, 2);
            if (tig == 0) atomicAdd(&ssq_ks[mi * 16 + h * 8 + grp], u);
        }
    __syncthreads();

    for (int i = t; i < 2304; i += 256) atomicAdd(&g_attn[bn * 2304 + i], attn_s[i]);
    if (t < 48) atomicAdd(&g_ssq_q[bn * 48 + t], ssq_qs[t]);
    else if (t < 96) atomicAdd(&g_ssq_k[bn * 48 + t - 48], ssq_ks[t - 48]);
}

// ---------------- softmax with l2-norm scaling + temperature ----------------
__global__ void softmax48_kernel(const float* __restrict__ temp)
{
    int row = blockIdx.x;
    int bn = row / CH;
    int n = bn & (HEADS - 1);
    int l = threadIdx.x;
    float tf = temp[n];
    float iq = rsqrtf(fmaxf(g_ssq_q[row], 1e-12f));
    float* arow = g_attn + (size_t)row * CH;

    float ik0 = rsqrtf(fmaxf(g_ssq_k[bn * CH + l], 1e-12f));
    float v0 = arow[l] * iq * ik0 * tf;
    float v1 = -3.0e38f;
    if (l < 16) {
        float ik1 = rsqrtf(fmaxf(g_ssq_k[bn * CH + l + 32], 1e-12f));
        v1 = arow[l + 32] * iq * ik1 * tf;
    }
    float m = fmaxf(v0, v1);
#pragma unroll
    for (int o = 16; o > 0; o >>= 1) m = fmaxf(m, __shfl_xor_sync(~0u, m, o));
    float e0 = expf(v0 - m);
    float e1 = (l < 16) ? expf(v1 - m) : 0.f;
    float s = e0 + e1;
#pragma unroll
    for (int o = 16; o > 0; o >>= 1) s += __shfl_xor_sync(~0u, s, o);
    float inv = 1.f / s;
    arow[l] = e0 * inv;
    if (l < 16) arow[l + 32] = e1 * inv;
}

// ---------------- out = attn @ V (fp16 V in, fp16 O out) ----------------
__global__ __launch_bounds__(256) void av_kernel()
{
    int bn = blockIdx.x;
    int s2 = blockIdx.y * 256 + threadIdx.x;

    __shared__ float As[CH * CH];
    for (int f = threadIdx.x; f < CH * CH; f += 256) As[f] = g_attn[bn * CH * CH + f];
    __syncthreads();

    const __half2* vb = (const __half2*)(g_v_h + (size_t)bn * CH * HW) + s2;
    float2 vr[CH];
#pragma unroll
    for (int e = 0; e < CH; e++) vr[e] = __half22float2(vb[(size_t)e * (HW / 2)]);

    __half2* ob = (__half2*)(g_o_h + (size_t)bn * CH * HW) + s2;
    for (int d = 0; d < CH; d++) {
        float2 a = make_float2(0.f, 0.f);
#pragma unroll
        for (int e = 0; e < CH; e++) {
            float w = As[d * CH + e];
            a.x = fmaf(w, vr[e].x, a.x);
            a.y = fmaf(w, vr[e].y, a.y);
        }
        ob[(size_t)d * (HW / 2)] = __floats2half2_rn(a.x, a.y);
    }
}

// ---------------- launch ----------------
extern "C" void kernel_launch(void* const* d_in, const int* in_sizes, int n_in,
                              void* d_out, int out_size)
{
    const float* x      = (const float*)d_in[0];
    const float* qkv_w  = (const float*)d_in[1];
    const float* dw_w   = (const float*)d_in[2];
    const float* proj_w = (const float*)d_in[3];
    const float* temp   = (const float*)d_in[4];
    float* out = (float*)d_out;

    __half *qkv_buf, *o_buf;
    cudaGetSymbolAddress((void**)&qkv_buf, g_qkv_h);
    cudaGetSymbolAddress((void**)&o_buf, g_o_h);
    __half *wq, *wp;
    cudaGetSymbolAddress((void**)&wq, g_wqkv);
    cudaGetSymbolAddress((void**)&wp, g_wproj);

    cudaFuncSetAttribute(gemm_fp16_1p<false, true>, cudaFuncAttributeMaxDynamicSharedMemorySize, GEMM_SMEM);
    cudaFuncSetAttribute(gemm_fp16_1p<true, false>, cudaFuncAttributeMaxDynamicSharedMemorySize, GEMM_SMEM);
    cudaFuncSetAttribute(qk_mma_kernel, cudaFuncAttributeMaxDynamicSharedMemorySize, QK_SMEM);

    const int M = NB * HW;

    // launches 1-3 (slot 4 = dwconv gets profiled)
    wprep_qkvw_kernel<<<(C3 * KDIM + 255) / 256, 256>>>(qkv_w);
    wprep_projw_kernel<<<(NC * KDIM + 255) / 256, 256>>>(proj_w);
    gemm_fp16_1p<false, true><<<M / 128, 128, GEMM_SMEM>>>(x, wq, qkv_buf, C3);

    // 4) depthwise 3x3 tiled v2 (coalesced)   <-- profiled slot
    dwconv_tiled2_kernel<<<dim3(18, 64, NB), 256>>>(dw_w);

    // 5) zero attn/ssq accumulators (needed before qk)
    zero_kernel<<<(BNT * CH * CH + 255) / 256, 256>>>();

    // 6) QK^T (tensor cores) + fused square sums
    qk_mma_kernel<<<dim3(BNT, 8), 256, QK_SMEM>>>();

    // 7) scale + softmax
    softmax48_kernel<<<BNT * CH, 32>>>(temp);

    // 8) out = attn @ V (fp16 -> fp16)
    av_kernel<<<dim3(BNT, HW / 512), 256>>>();

    // 9) projection (fp16 in, fp32 out)
    gemm_fp16_1p<true, false><<<M / 128, 128, GEMM_SMEM>>>(o_buf, wp, out, NC);
}